// round 9
// baseline (speedup 1.0000x reference)
#include <cuda_runtime.h>
#include <cstdint>

#define NIMG 64
#define CCH 256
#define KDIM (CCH*9)        // 2304
#define PIX 1024
#define BM 128
#define BN 128
#define BKC 16
#define KITERS (KDIM/BKC)   // 144
#define AS_STRIDE 20        // conflict-free for A fragment reads
#define BS_STRIDE 136       // conflict-free for B fragment reads

// Scratch (allocation-free rule: __device__ globals)
__device__ float g_xr[(size_t)NIMG*CCH*PIX];   // tf32-rounded x
__device__ float g_h [(size_t)NIMG*CCH*PIX];   // intermediate h (tf32-rounded)
__device__ float g_inv [2][CCH];
__device__ float g_bias[2][CCH];

__device__ __forceinline__ float tf32_rna(float x){
    float r; asm("cvt.rna.tf32.f32 %0, %1;" : "=f"(r) : "f"(x)); return r;
}

__global__ void bn_prep_kernel(const float* __restrict__ g1, const float* __restrict__ b1,
                               const float* __restrict__ rm1, const float* __restrict__ rv1,
                               const float* __restrict__ g2, const float* __restrict__ b2,
                               const float* __restrict__ rm2, const float* __restrict__ rv2){
    int i = threadIdx.x;
    if (i < CCH){
        float inv1 = g1[i]*rsqrtf(rv1[i]+1e-5f);
        g_inv[0][i]=inv1; g_bias[0][i]=b1[i]-rm1[i]*inv1;
        float inv2 = g2[i]*rsqrtf(rv2[i]+1e-5f);
        g_inv[1][i]=inv2; g_bias[1][i]=b2[i]-rm2[i]*inv2;
    }
}

__global__ void round_x_kernel(const float4* __restrict__ x){
    const int total = NIMG*CCH*PIX/4;
    float4* o = (float4*)g_xr;
    for (int i = blockIdx.x*blockDim.x + threadIdx.x; i < total; i += gridDim.x*blockDim.x){
        float4 v = x[i];
        v.x=tf32_rna(v.x); v.y=tf32_rna(v.y); v.z=tf32_rna(v.z); v.w=tf32_rna(v.w);
        o[i]=v;
    }
}

__device__ __forceinline__ void cp_async16(uint32_t s, const float* g){
    asm volatile("cp.async.ca.shared.global [%0], [%1], 16;\n" :: "r"(s), "l"(g));
}
__device__ __forceinline__ void cp_async4z(uint32_t s, const float* g, bool ok){
    int sz = ok ? 4 : 0;   // src-size 0 -> zero-fill, src not dereferenced
    asm volatile("cp.async.ca.shared.global [%0], [%1], 4, %2;\n" :: "r"(s), "l"(g), "r"(sz));
}
__device__ __forceinline__ void cp_commit(){ asm volatile("cp.async.commit_group;\n"); }
__device__ __forceinline__ void cp_wait0(){ asm volatile("cp.async.wait_group 0;\n"); }

__device__ __forceinline__ void mma_tf32(float* c, const uint32_t* a, const uint32_t* b){
    asm volatile("mma.sync.aligned.m16n8k8.row.col.f32.tf32.tf32.f32 "
        "{%0,%1,%2,%3}, {%4,%5,%6,%7}, {%8,%9}, {%0,%1,%2,%3};\n"
        : "+f"(c[0]), "+f"(c[1]), "+f"(c[2]), "+f"(c[3])
        : "r"(a[0]), "r"(a[1]), "r"(a[2]), "r"(a[3]), "r"(b[0]), "r"(b[1]));
}

// MODE 0: conv1: B = g_xr, out = g_h (BN1 + ReLU + tf32 round)
// MODE 1: conv2: B = g_h,  out = dout (BN2 + residual add + ReLU)
template<int MODE>
__global__ __launch_bounds__(256, 2)
void conv_kernel(const float* __restrict__ Wt, const float* __restrict__ resid,
                 float* __restrict__ dout){
    __shared__ float As[2][BM][AS_STRIDE];
    __shared__ float Bs[2][BKC][BS_STRIDE];

    const float* __restrict__ Bsrc = (MODE==0) ? g_xr : g_h;
    float* __restrict__ out = (MODE==0) ? g_h : dout;

    const int tid  = threadIdx.x;
    const int lane = tid & 31;
    const int warp = tid >> 5;
    const int qg = lane >> 2;     // octet group 0..7
    const int qt = lane & 3;      // 0..3
    const int wm = warp & 1;      // 2 warps along M
    const int wn = warp >> 1;     // 4 warps along N
    const int n   = blockIdx.z;
    const int co0 = blockIdx.y * BM;
    const int p0  = blockIdx.x * BN;

    // ---- A loader (weights, row-major [Cout][2304]) : 2x 16B cp.async per chunk ----
    const int a_m  = tid >> 1;
    const int a_k8 = (tid & 1) * 8;
    const float* a_g = Wt + (size_t)(co0 + a_m)*KDIM + a_k8;
    uint32_t a_s[2];
    a_s[0] = (uint32_t)__cvta_generic_to_shared(&As[0][a_m][a_k8]);
    a_s[1] = (uint32_t)__cvta_generic_to_shared(&As[1][a_m][a_k8]);

    // ---- B loader (im2col gather) : 8x 4B cp.async per chunk ----
    const int b_k  = tid >> 4;            // 0..15 (k within chunk)
    const int b_p  = (tid & 15) << 3;     // 0..120 (pixel within tile)
    const int b_h  = (p0 >> 5) + (b_p >> 5);  // image row (pre-offset); tile = 4 rows
    const int b_w0 = b_p & 31;
    uint32_t b_s[2];
    b_s[0] = (uint32_t)__cvta_generic_to_shared(&Bs[0][b_k][b_p]);
    b_s[1] = (uint32_t)__cvta_generic_to_shared(&Bs[1][b_k][b_p]);

    float acc[4][4][4];
    #pragma unroll
    for (int i=0;i<4;i++)
        #pragma unroll
        for (int j=0;j<4;j++)
            #pragma unroll
            for (int r=0;r<4;r++) acc[i][j][r] = 0.0f;

    auto LOAD = [&](int it, int buf){
        const int kb = it * BKC;
        cp_async16(a_s[buf],      a_g + kb);
        cp_async16(a_s[buf] + 16, a_g + kb + 4);
        const int kg  = kb + b_k;
        const int cin = kg / 9;
        const int rr  = kg - cin*9;
        const int dh  = rr / 3;
        const int dw  = rr - dh*3;
        const int hh  = b_h + dh - 1;
        const bool hok = ((unsigned)hh < 32u);
        const float* src = Bsrc + (((size_t)n*CCH + cin)*32 + hh)*32;
        #pragma unroll
        for (int pp=0; pp<8; pp++){
            const int wv = b_w0 + dw - 1 + pp;
            cp_async4z(b_s[buf] + pp*4, src + wv, hok && ((unsigned)wv < 32u));
        }
        cp_commit();
    };

    auto COMPUTE = [&](int buf){
        #pragma unroll
        for (int ks=0; ks<2; ks++){
            uint32_t a[4][4], b[4][2];
            const int kk = ks*8 + qt;
            #pragma unroll
            for (int mt=0; mt<4; mt++){
                const int m = wm*64 + mt*16 + qg;
                a[mt][0] = __float_as_uint(As[buf][m  ][kk  ]);
                a[mt][1] = __float_as_uint(As[buf][m+8][kk  ]);
                a[mt][2] = __float_as_uint(As[buf][m  ][kk+4]);
                a[mt][3] = __float_as_uint(As[buf][m+8][kk+4]);
            }
            #pragma unroll
            for (int nt=0; nt<4; nt++){
                const int cb = wn*32 + nt*8 + qg;
                b[nt][0] = __float_as_uint(Bs[buf][kk  ][cb]);
                b[nt][1] = __float_as_uint(Bs[buf][kk+4][cb]);
            }
            #pragma unroll
            for (int mt=0; mt<4; mt++)
                #pragma unroll
                for (int nt=0; nt<4; nt++)
                    mma_tf32(acc[mt][nt], a[mt], b[nt]);
        }
    };

    LOAD(0, 0);
    #pragma unroll 1
    for (int it=0; it<KITERS; it++){
        const int buf = it & 1;
        cp_wait0();
        __syncthreads();
        if (it + 1 < KITERS) LOAD(it+1, buf^1);
        COMPUTE(buf);
    }

    // ---- fused epilogue ----
    const float* __restrict__ inv  = g_inv[MODE];
    const float* __restrict__ bias = g_bias[MODE];
    #pragma unroll
    for (int mt=0; mt<4; mt++){
        const int co = co0 + wm*64 + mt*16 + qg;
        const float i0 = inv[co],   s0 = bias[co];
        const float i1 = inv[co+8], s1 = bias[co+8];
        #pragma unroll
        for (int nt=0; nt<4; nt++){
            const int p = p0 + wn*32 + nt*8 + 2*qt;
            const size_t o0 = ((size_t)n*CCH + co)*PIX + p;
            const size_t o1 = o0 + (size_t)8*PIX;
            float v0 = fmaf(acc[mt][nt][0], i0, s0);
            float v1 = fmaf(acc[mt][nt][1], i0, s0);
            float v2 = fmaf(acc[mt][nt][2], i1, s1);
            float v3 = fmaf(acc[mt][nt][3], i1, s1);
            if (MODE == 0){
                v0 = tf32_rna(fmaxf(v0, 0.0f));
                v1 = tf32_rna(fmaxf(v1, 0.0f));
                v2 = tf32_rna(fmaxf(v2, 0.0f));
                v3 = tf32_rna(fmaxf(v3, 0.0f));
            } else {
                const float2 r0 = *(const float2*)(resid + o0);
                const float2 r1 = *(const float2*)(resid + o1);
                v0 = fmaxf(r0.x + v0, 0.0f);
                v1 = fmaxf(r0.y + v1, 0.0f);
                v2 = fmaxf(r1.x + v2, 0.0f);
                v3 = fmaxf(r1.y + v3, 0.0f);
            }
            float2 w0; w0.x = v0; w0.y = v1;
            float2 w1; w1.x = v2; w1.y = v3;
            *(float2*)(out + o0) = w0;
            *(float2*)(out + o1) = w1;
        }
    }
}

extern "C" void kernel_launch(void* const* d_in, const int* in_sizes, int n_in,
                              void* d_out, int out_size){
    const float* x   = (const float*)d_in[0];
    const float* w1  = (const float*)d_in[1];
    const float* g1  = (const float*)d_in[2];
    const float* b1  = (const float*)d_in[3];
    const float* rm1 = (const float*)d_in[4];
    const float* rv1 = (const float*)d_in[5];
    const float* w2  = (const float*)d_in[6];
    const float* g2  = (const float*)d_in[7];
    const float* b2  = (const float*)d_in[8];
    const float* rm2 = (const float*)d_in[9];
    const float* rv2 = (const float*)d_in[10];
    float* out = (float*)d_out;

    bn_prep_kernel<<<1, CCH>>>(g1,b1,rm1,rv1,g2,b2,rm2,rv2);
    round_x_kernel<<<2048, 256>>>((const float4*)x);

    dim3 grid(PIX/BN, CCH/BM, NIMG);   // (8, 2, 64)
    conv_kernel<0><<<grid, 256>>>(w1, nullptr, nullptr);
    conv_kernel<1><<<grid, 256>>>(w2, x, out);
}

// round 11
// speedup vs baseline: 3.7434x; 3.7434x over previous
#include <cuda_runtime.h>
#include <cuda_fp16.h>
#include <cstdint>

#define NIMG 64
#define CCH 256
#define NCHUNK 16            // 16 cins per chunk
#define STAGE 52992          // A 38912 + B 14080
#define NSTAGE 4
#define SMEM_BYTES (NSTAGE*STAGE)   // 211968

// ---- scratch (__device__ globals; no allocation) ----
__device__ __half2 g_x16[(size_t)NIMG*128*1024];   // packed: [img][cpair][pix] = {c2i, c2i+1}
__device__ __half2 g_h16[(size_t)NIMG*128*1024];   // intermediate h, same layout
__device__ __half  g_w1h[(size_t)CCH*2304];        // k' = chunk*144 + off*16 + ci
__device__ __half  g_w2h[(size_t)CCH*2304];
__device__ float   g_inv [2][CCH];
__device__ float   g_bias[2][CCH];

__global__ void bn_prep_kernel(const float* __restrict__ g1, const float* __restrict__ b1,
                               const float* __restrict__ rm1, const float* __restrict__ rv1,
                               const float* __restrict__ g2, const float* __restrict__ b2,
                               const float* __restrict__ rm2, const float* __restrict__ rv2){
    int i = threadIdx.x;
    if (i < CCH){
        float i1 = g1[i]*rsqrtf(rv1[i]+1e-5f);
        g_inv[0][i]=i1; g_bias[0][i]=b1[i]-rm1[i]*i1;
        float i2 = g2[i]*rsqrtf(rv2[i]+1e-5f);
        g_inv[1][i]=i2; g_bias[1][i]=b2[i]-rm2[i]*i2;
    }
}

// x fp32 NCHW -> packed channel-pair fp16
__global__ void pack_x_kernel(const float* __restrict__ x){
    int i = blockIdx.x*blockDim.x + threadIdx.x;        // 32768*256 = 8388608 exact
    int pix = i & 1023, pr = (i >> 10) & 127, img = i >> 17;
    size_t b = ((size_t)(img*256 + 2*pr))*1024 + pix;
    g_x16[i] = __floats2half2_rn(x[b], x[b + 1024]);
}

// W[co][cin][3][3] -> fp16 Wt[co][chunk*144 + off*16 + ci],  cin = chunk*16+ci
__global__ void wtrans_kernel(const float* __restrict__ w1, const float* __restrict__ w2){
    int i = blockIdx.x*blockDim.x + threadIdx.x;        // 2304*256 = 589824 exact
    int co = i / 2304, k = i - co*2304;
    int chunk = k / 144, r = k - chunk*144, off = r >> 4, ci = r & 15;
    int src = co*2304 + (chunk*16 + ci)*9 + off;
    g_w1h[i] = __float2half_rn(w1[src]);
    g_w2h[i] = __float2half_rn(w2[src]);
}

// ---- PTX helpers ----
__device__ __forceinline__ void cp16(uint32_t d, const void* g){
    asm volatile("cp.async.cg.shared.global [%0], [%1], 16;\n" :: "r"(d), "l"(g));
}
__device__ __forceinline__ void cp16z(uint32_t d, const void* g, int ok){
    int sz = ok ? 16 : 0;
    asm volatile("cp.async.cg.shared.global [%0], [%1], 16, %2;\n" :: "r"(d), "l"(g), "r"(sz));
}
__device__ __forceinline__ void ldsm4(uint32_t* r, uint32_t a){
    asm volatile("ldmatrix.sync.aligned.m8n8.x4.shared.b16 {%0,%1,%2,%3}, [%4];"
                 : "=r"(r[0]), "=r"(r[1]), "=r"(r[2]), "=r"(r[3]) : "r"(a));
}
__device__ __forceinline__ uint32_t lds32(uint32_t a){
    uint32_t v; asm volatile("ld.shared.b32 %0, [%1];" : "=r"(v) : "r"(a)); return v;
}
__device__ __forceinline__ void mma16(float* c, const uint32_t* a, const uint32_t* b){
    asm volatile("mma.sync.aligned.m16n8k16.row.col.f32.f16.f16.f32 "
        "{%0,%1,%2,%3}, {%4,%5,%6,%7}, {%8,%9}, {%0,%1,%2,%3};\n"
        : "+f"(c[0]), "+f"(c[1]), "+f"(c[2]), "+f"(c[3])
        : "r"(a[0]), "r"(a[1]), "r"(a[2]), "r"(a[3]), "r"(b[0]), "r"(b[1]));
}

// MODE 0: B = g_x16, out = g_h16 (BN1+ReLU, fp16 packed)
// MODE 1: B = g_h16, out = dout fp32 (BN2 + residual + ReLU)
template<int MODE>
__global__ __launch_bounds__(256,1)
void conv_f16(const float* __restrict__ resid, float* __restrict__ dout){
    extern __shared__ char smem[];
    uint32_t sb = (uint32_t)__cvta_generic_to_shared(smem);
    const int tid = threadIdx.x, lane = tid & 31, warp = tid >> 5;
    const int qg = lane >> 2, qt = lane & 3, wm = warp & 1, wn = warp >> 1;
    const int bx = blockIdx.x, img = blockIdx.z, co0 = blockIdx.y*128, r0 = bx*8;

    const __half*  Wt   = (MODE==0) ? g_w1h : g_w2h;
    const __half2* Bsrc = (MODE==0) ? g_x16 : g_h16;

    // ---- pre-zero halo columns (u4 cols 7 and 40 of every B row, all stages) ----
    for (int z = tid; z < 640; z += 256){
        int s = z/160, r2 = z - s*160, pr = r2/20, r3 = r2 - pr*20, slot = r3 >> 1, side = r3 & 1;
        uint32_t ad = sb + (uint32_t)(s*STAGE + 38912 + (pr*440 + slot*44 + (side?40:7))*4);
        asm volatile("st.shared.u32 [%0], %1;" :: "r"(ad), "r"(0));
    }

    // ---- loader precompute ----
    uint32_t a_dst[9], a_off[9];                 // A: 2304 16B ops/chunk, 9/thread
    #pragma unroll
    for (int j = 0; j < 9; j++){
        int o = tid + j*256, row = o/18, seg = o - row*18;
        a_dst[j] = (uint32_t)(row*304 + seg*16);
        a_off[j] = (uint32_t)((co0 + row)*2304 + seg*8);   // halves
    }
    uint32_t b_dst[3], b_off[3]; int b_ok[3];    // B: 640 16B ops/chunk
    #pragma unroll
    for (int j = 0; j < 3; j++){
        int o = tid + j*256;
        if (o < 640){
            int pr = o/80, rem = o - pr*80, slot = rem >> 3, seg = rem & 7;
            int gr = r0 + slot - 1;
            b_ok[j] = ((unsigned)gr < 32u) ? 1 : 0;
            b_dst[j] = (uint32_t)(38912 + pr*1760 + slot*176 + 32 + seg*16);
            b_off[j] = (uint32_t)((img*128 + pr)*1024 + (b_ok[j] ? gr : 0)*32 + seg*4); // half2 elems
        } else b_ok[j] = -1;
    }

    float acc[4][8][4];
    #pragma unroll
    for (int i=0;i<4;i++)
        #pragma unroll
        for (int j=0;j<8;j++)
            #pragma unroll
            for (int r=0;r<4;r++) acc[i][j][r] = 0.0f;

    auto LOAD = [&](int c){
        uint32_t s = sb + (uint32_t)((c & 3)*STAGE);
        #pragma unroll
        for (int j = 0; j < 9; j++) cp16(s + a_dst[j], Wt + a_off[j] + c*144);
        #pragma unroll
        for (int j = 0; j < 3; j++)
            if (b_ok[j] >= 0) cp16z(s + b_dst[j], Bsrc + b_off[j] + c*8192, b_ok[j]);
        asm volatile("cp.async.commit_group;\n");
    };

    LOAD(0); LOAD(1); LOAD(2);

    #pragma unroll 1
    for (int c = 0; c < NCHUNK; c++){
        if (c < NCHUNK-2)      asm volatile("cp.async.wait_group 2;\n");
        else if (c == NCHUNK-2) asm volatile("cp.async.wait_group 1;\n");
        else                    asm volatile("cp.async.wait_group 0;\n");
        __syncthreads();
        if (c + 3 < NCHUNK) LOAD(c+3);

        const uint32_t sA = sb + (uint32_t)((c & 3)*STAGE);
        const uint32_t sB = sA + 38912;
        #pragma unroll
        for (int off = 0; off < 9; off++){
            const int dh = off/3, dw = off - 3*(off/3);
            uint32_t a[4][4];
            #pragma unroll
            for (int mt = 0; mt < 4; mt++){
                uint32_t ad = sA + (uint32_t)((wm*64 + mt*16 + (lane & 15))*304
                                              + off*32 + ((lane >> 4) << 4));
                ldsm4(a[mt], ad);
            }
            uint32_t b[8][2];
            #pragma unroll
            for (int nt = 0; nt < 8; nt++){
                const int pxb = wn*64 + nt*8;
                uint32_t ad = sB + (uint32_t)((qt*440 + ((pxb >> 5) + dh)*44
                                               + 7 + (pxb & 31) + dw + qg)*4);
                b[nt][0] = lds32(ad);
                b[nt][1] = lds32(ad + 7040);     // pair qt+4
            }
            #pragma unroll
            for (int mt = 0; mt < 4; mt++)
                #pragma unroll
                for (int nt = 0; nt < 8; nt++)
                    mma16(acc[mt][nt], a[mt], b[nt]);
        }
    }

    // ---------------- epilogue ----------------
    if (MODE == 0){
        char* Sw = smem + warp*9216;             // per-warp staging [64][72] halves
        #pragma unroll
        for (int mt = 0; mt < 4; mt++){
            const int co = co0 + wm*64 + mt*16 + qg;
            const float i0 = g_inv[0][co],   s0 = g_bias[0][co];
            const float i1 = g_inv[0][co+8], s1 = g_bias[0][co+8];
            #pragma unroll
            for (int nt = 0; nt < 8; nt++){
                const int pxl = nt*8 + 2*qt;
                float v0 = fmaxf(fmaf(acc[mt][nt][0], i0, s0), 0.f);
                float v1 = fmaxf(fmaf(acc[mt][nt][1], i0, s0), 0.f);
                float v2 = fmaxf(fmaf(acc[mt][nt][2], i1, s1), 0.f);
                float v3 = fmaxf(fmaf(acc[mt][nt][3], i1, s1), 0.f);
                *(__half2*)(Sw + ((mt*16 + qg    )*72 + pxl)*2) = __floats2half2_rn(v0, v1);
                *(__half2*)(Sw + ((mt*16 + qg + 8)*72 + pxl)*2) = __floats2half2_rn(v2, v3);
            }
        }
        __syncwarp();
        #pragma unroll
        for (int it = 0; it < 16; it++){
            const int cpl = it*2 + (lane >> 4), px4 = lane & 15;
            uint2 lo = *(uint2*)(Sw + ((2*cpl    )*72 + px4*4)*2);
            uint2 hi = *(uint2*)(Sw + ((2*cpl + 1)*72 + px4*4)*2);
            uint4 v;
            v.x = __byte_perm(lo.x, hi.x, 0x5410);
            v.y = __byte_perm(lo.x, hi.x, 0x7632);
            v.z = __byte_perm(lo.y, hi.y, 0x5410);
            v.w = __byte_perm(lo.y, hi.y, 0x7632);
            size_t idx = ((size_t)(img*128 + (co0 >> 1) + wm*32 + cpl))*1024
                       + bx*256 + wn*64 + px4*4;
            *(uint4*)((uint32_t*)g_h16 + idx) = v;
        }
    } else {
        #pragma unroll
        for (int mt = 0; mt < 4; mt++){
            const int co = co0 + wm*64 + mt*16 + qg;
            const float i0 = g_inv[1][co],   s0 = g_bias[1][co];
            const float i1 = g_inv[1][co+8], s1 = g_bias[1][co+8];
            #pragma unroll
            for (int nt = 0; nt < 8; nt++){
                const int p = bx*256 + wn*64 + nt*8 + 2*qt;
                const size_t o0 = ((size_t)(img*256 + co))*1024 + p;
                const size_t o1 = o0 + 8*1024;
                const float2 r0 = *(const float2*)(resid + o0);
                const float2 r1 = *(const float2*)(resid + o1);
                float2 w0, w1;
                w0.x = fmaxf(fmaf(acc[mt][nt][0], i0, s0) + r0.x, 0.f);
                w0.y = fmaxf(fmaf(acc[mt][nt][1], i0, s0) + r0.y, 0.f);
                w1.x = fmaxf(fmaf(acc[mt][nt][2], i1, s1) + r1.x, 0.f);
                w1.y = fmaxf(fmaf(acc[mt][nt][3], i1, s1) + r1.y, 0.f);
                *(float2*)(dout + o0) = w0;
                *(float2*)(dout + o1) = w1;
            }
        }
    }
}

extern "C" void kernel_launch(void* const* d_in, const int* in_sizes, int n_in,
                              void* d_out, int out_size){
    const float* x   = (const float*)d_in[0];
    const float* w1  = (const float*)d_in[1];
    const float* g1  = (const float*)d_in[2];
    const float* b1  = (const float*)d_in[3];
    const float* rm1 = (const float*)d_in[4];
    const float* rv1 = (const float*)d_in[5];
    const float* w2  = (const float*)d_in[6];
    const float* g2  = (const float*)d_in[7];
    const float* b2  = (const float*)d_in[8];
    const float* rm2 = (const float*)d_in[9];
    const float* rv2 = (const float*)d_in[10];
    float* out = (float*)d_out;

    bn_prep_kernel<<<1, 256>>>(g1,b1,rm1,rv1,g2,b2,rm2,rv2);
    pack_x_kernel<<<32768, 256>>>(x);
    wtrans_kernel<<<2304, 256>>>(w1, w2);

    cudaFuncSetAttribute(conv_f16<0>, cudaFuncAttributeMaxDynamicSharedMemorySize, SMEM_BYTES);
    cudaFuncSetAttribute(conv_f16<1>, cudaFuncAttributeMaxDynamicSharedMemorySize, SMEM_BYTES);
    dim3 grid(4, 2, NIMG);   // 512 CTAs
    conv_f16<0><<<grid, 256, SMEM_BYTES>>>(nullptr, nullptr);
    conv_f16<1><<<grid, 256, SMEM_BYTES>>>(x, out);
}